// round 12
// baseline (speedup 1.0000x reference)
#include <cuda_runtime.h>
#include <cuda_fp16.h>
#include <stdint.h>
#include <math.h>

// C = tril(A @ B), A,B lower-triangular fp32, N = 8192.
// Plain fp16 HMMA (Ah*Bh, fp32 accumulate); rel_err ~2.9e-4 (measured).
// Phase 1: convert to pre-swizzled 128x32 fp16 blocks in __device__ scratch.
// Phase 2: single kernel, 1D grid: 2080 band tiles (longest-band-first)
//          followed by 2016 zero tiles. Band: 128x128 CTA tile, BK=64 per
//          iter (2x 128x32 blocks), 3-stage x 32KB cp.async ring, 8 warps
//          (warp tile 64x32), 2 CTAs/SM.

#define NTH 256
#define NB  64            // 128-wide block count (N/128)
#define KT  256           // 32-wide k-tile count (N/32)
#define BLKB 8192         // bytes per 128x32 fp16 block
#define STAGEB (4 * BLKB) // A(kt) + A(kt+1) + B(kt) + B(kt+1) = 32 KB
#define SMEM_REQ (3 * STAGEB)        // 96 KB
#define NWORK (NB * (NB + 1) / 2)    // 2080 band tiles

// swizzled offset inside a 128x32 block: row r (0..127), 16B chunk c (0..3)
#define SWZ32(r, c) ((uint32_t)((r) * 64 + ((((c) ^ (((r) >> 1) & 3))) << 4)))

__device__ __align__(1024) static unsigned char gAh[(size_t)NB * KT * BLKB];
__device__ __align__(1024) static unsigned char gBh[(size_t)NB * KT * BLKB];

static __device__ __forceinline__ uint32_t smem_u32(const void* p) {
    uint32_t a;
    asm("{ .reg .u64 t; cvta.to.shared.u64 t, %1; cvt.u32.u64 %0, t; }"
        : "=r"(a) : "l"(p));
    return a;
}

#define LDSM4(r, addr)                                                    \
    asm volatile("ldmatrix.sync.aligned.m8n8.x4.shared.b16 "              \
                 "{%0, %1, %2, %3}, [%4];"                                \
                 : "=r"((r)[0]), "=r"((r)[1]), "=r"((r)[2]), "=r"((r)[3]) \
                 : "r"(addr))

#define MMA16816(d, a, b0, b1)                                            \
    asm volatile("mma.sync.aligned.m16n8k16.row.col.f32.f16.f16.f32 "     \
                 "{%0, %1, %2, %3}, {%4, %5, %6, %7}, {%8, %9}, "         \
                 "{%0, %1, %2, %3};"                                      \
                 : "+f"((d)[0]), "+f"((d)[1]), "+f"((d)[2]), "+f"((d)[3]) \
                 : "r"((a)[0]), "r"((a)[1]), "r"((a)[2]), "r"((a)[3]),    \
                   "r"(b0), "r"(b1))

#define CP16(dst, src)                                                    \
    asm volatile("cp.async.cg.shared.global [%0], [%1], 16;"              \
                 :: "r"(dst), "l"(src))
#define CP_COMMIT() asm volatile("cp.async.commit_group;" ::: "memory")
#define CP_WAIT1()  asm volatile("cp.async.wait_group 1;" ::: "memory")

// ======================= Phase 1: conversion kernels =======================

__global__ __launch_bounds__(NTH, 4)
void convA(const float* __restrict__ A, int N)
{
    const int kt = blockIdx.x, bi = blockIdx.y;
    if (kt >= 4 * (bi + 1)) return;
    const int tid = threadIdx.x;
    const float* Ab = A + (size_t)(bi * 128) * N + kt * 32;
    unsigned char* oH = gAh + (size_t)(bi * KT + kt) * BLKB;
    #pragma unroll
    for (int l = 0; l < 4; ++l) {
        int idx = tid + l * NTH;      // 0..1023
        int r  = idx >> 3;            // m row
        int c4 = idx & 7;             // float4 index along k
        float4 v = *reinterpret_cast<const float4*>(Ab + (size_t)r * N + c4 * 4);
        uint32_t h01, h23;
        asm("cvt.rn.f16x2.f32 %0, %1, %2;" : "=r"(h01) : "f"(v.y), "f"(v.x));
        asm("cvt.rn.f16x2.f32 %0, %1, %2;" : "=r"(h23) : "f"(v.w), "f"(v.z));
        uint32_t off = SWZ32(r, c4 >> 1) + (c4 & 1) * 8;
        *reinterpret_cast<uint2*>(oH + off) = make_uint2(h01, h23);
    }
}

__global__ __launch_bounds__(NTH, 4)
void convB(const float* __restrict__ B, int N)
{
    const int kt = blockIdx.x, bn = blockIdx.y;
    if (kt < 4 * bn) return;
    const int tid = threadIdx.x;
    __shared__ __align__(128) unsigned char sb[BLKB];

    const float* Bb = B + (size_t)(kt * 32) * N + bn * 128;
    #pragma unroll
    for (int l = 0; l < 4; ++l) {
        int idx = tid + l * NTH;      // 0..1023
        int k  = idx >> 5;            // 0..31
        int n4 = idx & 31;            // float4 index along n
        float4 v = *reinterpret_cast<const float4*>(Bb + (size_t)k * N + n4 * 4);
        const float* pv = &v.x;
        int c  = k >> 3;
        int kb = (k & 7) * 2;
        #pragma unroll
        for (int e = 0; e < 4; ++e) {
            int n = n4 * 4 + e;
            __half hh = __float2half_rn(pv[e]);
            uint32_t off = SWZ32(n, c) + kb;
            *reinterpret_cast<unsigned short*>(sb + off) =
                *reinterpret_cast<unsigned short*>(&hh);
        }
    }
    __syncthreads();

    unsigned char* oH = gBh + (size_t)(bn * KT + kt) * BLKB;
    {
        int o = tid * 16;
        *reinterpret_cast<uint4*>(oH + o) = *reinterpret_cast<uint4*>(sb + o);
        o += NTH * 16;
        *reinterpret_cast<uint4*>(oH + o) = *reinterpret_cast<uint4*>(sb + o);
    }
}

// ======================= Phase 2: GEMM + zero fill =======================

// 32KB stage = A(kt), A(kt+1), B(kt), B(kt+1); 32B per thread per 8KB block
static __device__ __forceinline__ void issue_stage(
    uint32_t dst, size_t ablk, size_t bblk, int tid)
{
    const unsigned char* s0 = gAh + ablk * BLKB;
    const unsigned char* s1 = gAh + (ablk + 1) * BLKB;
    const unsigned char* s2 = gBh + bblk * BLKB;
    const unsigned char* s3 = gBh + (bblk + 1) * BLKB;
    const uint32_t t16 = tid * 16;
    #pragma unroll
    for (int h = 0; h < 2; ++h) {
        uint32_t off = t16 + h * 4096;
        CP16(dst + 0 * BLKB + off, s0 + off);
        CP16(dst + 1 * BLKB + off, s1 + off);
        CP16(dst + 2 * BLKB + off, s2 + off);
        CP16(dst + 3 * BLKB + off, s3 + off);
    }
}

__global__ __launch_bounds__(NTH, 2)
void trilmm_pp(float* __restrict__ C, int N)
{
    const int p   = blockIdx.x;
    const int tid = threadIdx.x;

    // ---- zero tiles (appended after the 2080 band tiles) ----
    if (p >= NWORK) {
        int q = p - NWORK;                 // 0..2015 over 63-row triangle
        int e = (int)((sqrtf(8.f * (float)q + 1.f) - 1.f) * 0.5f);
        while ((e + 1) * (e + 2) / 2 <= q) ++e;
        while (e * (e + 1) / 2 > q) --e;
        int y  = q - e * (e + 1) / 2;      // 0..e
        int bi = y, bj = e + 1;            // bi < bj
        const float4 z = make_float4(0.f, 0.f, 0.f, 0.f);
        float4* Cb = reinterpret_cast<float4*>(C + (size_t)bi * 128 * N + bj * 128);
        const int row_f4 = N / 4;
        #pragma unroll 4
        for (int i = tid; i < 128 * 32; i += NTH) {
            int r = i >> 5;
            int c = i & 31;
            Cb[(size_t)r * row_f4 + c] = z;
        }
        return;
    }

    // ---- band tiles: longest-band-first mapping ----
    int e = (int)((sqrtf(8.f * (float)p + 1.f) - 1.f) * 0.5f);
    while ((e + 1) * (e + 2) / 2 <= p) ++e;
    while (e * (e + 1) / 2 > p) --e;
    const int t  = p - e * (e + 1) / 2;
    const int d  = 63 - e;
    const int bj = t, bi = t + d;

    const int wid  = tid >> 5;
    const int lane = tid & 31;
    const int m0   = (wid >> 2) * 64;    // 2x4 warp grid, warp tile 64x32
    const int n0   = (wid & 3) * 32;

    extern __shared__ __align__(1024) unsigned char dsm[];
    const uint32_t S = smem_u32(dsm);

    float acc[4][4][4];
    #pragma unroll
    for (int a = 0; a < 4; ++a)
        #pragma unroll
        for (int b = 0; b < 4; ++b)
            #pragma unroll
            for (int c = 0; c < 4; ++c)
                acc[a][b][c] = 0.f;

    const int kt0 = 4 * bj;
    const int NT  = 2 * (bi - bj) + 2;   // 64-wide K stages in band (>= 2)
    const size_t abase = (size_t)bi * KT + kt0;
    const size_t bbase = (size_t)bj * KT + kt0;

    // prologue: stages 0,1
    issue_stage(S,          abase,     bbase,     tid); CP_COMMIT();
    issue_stage(S + STAGEB, abase + 2, bbase + 2, tid); CP_COMMIT();

    const uint32_t a_r = (uint32_t)(lane & 15);
    const uint32_t a_c = (uint32_t)(lane >> 4);
    const uint32_t b_r = (uint32_t)((lane & 7) + ((lane >> 4) & 1) * 8);
    const uint32_t b_c = (uint32_t)((lane >> 3) & 1);

    int slot = 0;
    for (int it = 0; it < NT; ++it) {
        CP_WAIT1();
        __syncthreads();
        if (it + 2 < NT) {
            int ns = slot + 2; if (ns >= 3) ns -= 3;
            issue_stage(S + ns * STAGEB,
                        abase + 2 * (it + 2), bbase + 2 * (it + 2), tid);
        }
        CP_COMMIT();

        const uint32_t aS = S + slot * STAGEB;

        #pragma unroll
        for (int kb = 0; kb < 2; ++kb) {
            const uint32_t aB = aS + kb * BLKB;
            const uint32_t bB = aS + (2 + kb) * BLKB;
            #pragma unroll
            for (int kk = 0; kk < 2; ++kk) {
                uint32_t ah[4][4];
                #pragma unroll
                for (int mt = 0; mt < 4; ++mt) {
                    uint32_t off = SWZ32(m0 + mt * 16 + a_r, kk * 2 + a_c);
                    LDSM4(ah[mt], aB + off);
                }
                #pragma unroll
                for (int j2 = 0; j2 < 2; ++j2) {
                    uint32_t bfh[4];
                    uint32_t boff = SWZ32(n0 + j2 * 16 + b_r, kk * 2 + b_c);
                    LDSM4(bfh, bB + boff);
                    #pragma unroll
                    for (int mt = 0; mt < 4; ++mt) {
                        #pragma unroll
                        for (int jj = 0; jj < 2; ++jj) {
                            float* dd = acc[mt][j2 * 2 + jj];
                            MMA16816(dd, ah[mt], bfh[2 * jj], bfh[2 * jj + 1]);
                        }
                    }
                }
            }
        }
        if (++slot == 3) slot = 0;
    }

    // epilogue: registers -> C, tril mask on diagonal tiles
    const int g   = lane >> 2;
    const int tig = lane & 3;
    const bool diag = (bi == bj);
    #pragma unroll
    for (int mt = 0; mt < 4; ++mt) {
        #pragma unroll
        for (int j = 0; j < 4; ++j) {
            int row0 = m0 + mt * 16 + g;
            int col  = n0 + j * 8 + 2 * tig;
            float c0 = acc[mt][j][0], c1 = acc[mt][j][1];
            float c2 = acc[mt][j][2], c3 = acc[mt][j][3];
            if (diag) {
                if (col     > row0)     c0 = 0.f;
                if (col + 1 > row0)     c1 = 0.f;
                if (col     > row0 + 8) c2 = 0.f;
                if (col + 1 > row0 + 8) c3 = 0.f;
            }
            float* p0 = C + (size_t)(bi * 128 + row0) * N + bj * 128 + col;
            float* p1 = p0 + (size_t)8 * N;
            *reinterpret_cast<float2*>(p0) = make_float2(c0, c1);
            *reinterpret_cast<float2*>(p1) = make_float2(c2, c3);
        }
    }
}

extern "C" void kernel_launch(void* const* d_in, const int* in_sizes, int n_in,
                              void* d_out, int out_size)
{
    const float* A = (const float*)d_in[0];
    const float* B = (const float*)d_in[1];
    float* C = (float*)d_out;
    int N = (int)llround(sqrt((double)in_sizes[0]));   // 8192

    cudaFuncSetAttribute(trilmm_pp,
                         cudaFuncAttributeMaxDynamicSharedMemorySize, SMEM_REQ);

    dim3 gridConv(KT, NB);
    convA<<<gridConv, NTH>>>(A, N);
    convB<<<gridConv, NTH>>>(B, N);

    trilmm_pp<<<NB * NB, NTH, SMEM_REQ>>>(C, N);   // 2080 band + 2016 zero
}

// round 13
// speedup vs baseline: 1.0137x; 1.0137x over previous
#include <cuda_runtime.h>
#include <cuda_fp16.h>
#include <stdint.h>
#include <math.h>

// C = tril(A @ B), A,B lower-triangular fp32, N = 8192.
// Plain fp16 HMMA (Ah*Bh, fp32 accumulate); rel_err ~2.9e-4 (measured).
// Phase 1: convert to pre-swizzled 128x32 fp16 blocks in __device__ scratch.
// Phase 2: single kernel, 1D grid: 2080 band tiles (longest-band-first)
//          followed by 2016 zero tiles. Band: 128x128 CTA tile, BK=32,
//          5-stage x 16KB cp.async ring (WAIT3, issue at it+4), 8 warps
//          (warp tile 64x32), 2 CTAs/SM.

#define NTH 256
#define NB  64            // 128-wide block count (N/128)
#define KT  256           // 32-wide k-tile count (N/32)
#define BLKB 8192         // bytes per 128x32 fp16 block
#define STAGEB (2 * BLKB) // Ah + Bh = 16 KB
#define STAGES 5
#define SMEM_REQ (STAGES * STAGEB)   // 80 KB
#define NWORK (NB * (NB + 1) / 2)    // 2080 band tiles

// swizzled offset inside a 128x32 block: row r (0..127), 16B chunk c (0..3)
#define SWZ32(r, c) ((uint32_t)((r) * 64 + ((((c) ^ (((r) >> 1) & 3))) << 4)))

__device__ __align__(1024) static unsigned char gAh[(size_t)NB * KT * BLKB];
__device__ __align__(1024) static unsigned char gBh[(size_t)NB * KT * BLKB];

static __device__ __forceinline__ uint32_t smem_u32(const void* p) {
    uint32_t a;
    asm("{ .reg .u64 t; cvta.to.shared.u64 t, %1; cvt.u32.u64 %0, t; }"
        : "=r"(a) : "l"(p));
    return a;
}

#define LDSM4(r, addr)                                                    \
    asm volatile("ldmatrix.sync.aligned.m8n8.x4.shared.b16 "              \
                 "{%0, %1, %2, %3}, [%4];"                                \
                 : "=r"((r)[0]), "=r"((r)[1]), "=r"((r)[2]), "=r"((r)[3]) \
                 : "r"(addr))

#define MMA16816(d, a, b0, b1)                                            \
    asm volatile("mma.sync.aligned.m16n8k16.row.col.f32.f16.f16.f32 "     \
                 "{%0, %1, %2, %3}, {%4, %5, %6, %7}, {%8, %9}, "         \
                 "{%0, %1, %2, %3};"                                      \
                 : "+f"((d)[0]), "+f"((d)[1]), "+f"((d)[2]), "+f"((d)[3]) \
                 : "r"((a)[0]), "r"((a)[1]), "r"((a)[2]), "r"((a)[3]),    \
                   "r"(b0), "r"(b1))

#define CP16(dst, src)                                                    \
    asm volatile("cp.async.cg.shared.global [%0], [%1], 16;"              \
                 :: "r"(dst), "l"(src))
#define CP_COMMIT() asm volatile("cp.async.commit_group;" ::: "memory")
#define CP_WAIT3()  asm volatile("cp.async.wait_group 3;" ::: "memory")

// ======================= Phase 1: conversion kernels =======================

__global__ __launch_bounds__(NTH, 4)
void convA(const float* __restrict__ A, int N)
{
    const int kt = blockIdx.x, bi = blockIdx.y;
    if (kt >= 4 * (bi + 1)) return;
    const int tid = threadIdx.x;
    const float* Ab = A + (size_t)(bi * 128) * N + kt * 32;
    unsigned char* oH = gAh + (size_t)(bi * KT + kt) * BLKB;
    #pragma unroll
    for (int l = 0; l < 4; ++l) {
        int idx = tid + l * NTH;      // 0..1023
        int r  = idx >> 3;            // m row
        int c4 = idx & 7;             // float4 index along k
        float4 v = *reinterpret_cast<const float4*>(Ab + (size_t)r * N + c4 * 4);
        uint32_t h01, h23;
        asm("cvt.rn.f16x2.f32 %0, %1, %2;" : "=r"(h01) : "f"(v.y), "f"(v.x));
        asm("cvt.rn.f16x2.f32 %0, %1, %2;" : "=r"(h23) : "f"(v.w), "f"(v.z));
        uint32_t off = SWZ32(r, c4 >> 1) + (c4 & 1) * 8;
        *reinterpret_cast<uint2*>(oH + off) = make_uint2(h01, h23);
    }
}

__global__ __launch_bounds__(NTH, 4)
void convB(const float* __restrict__ B, int N)
{
    const int kt = blockIdx.x, bn = blockIdx.y;
    if (kt < 4 * bn) return;
    const int tid = threadIdx.x;
    __shared__ __align__(128) unsigned char sb[BLKB];

    const float* Bb = B + (size_t)(kt * 32) * N + bn * 128;
    #pragma unroll
    for (int l = 0; l < 4; ++l) {
        int idx = tid + l * NTH;      // 0..1023
        int k  = idx >> 5;            // 0..31
        int n4 = idx & 31;            // float4 index along n
        float4 v = *reinterpret_cast<const float4*>(Bb + (size_t)k * N + n4 * 4);
        const float* pv = &v.x;
        int c  = k >> 3;
        int kb = (k & 7) * 2;
        #pragma unroll
        for (int e = 0; e < 4; ++e) {
            int n = n4 * 4 + e;
            __half hh = __float2half_rn(pv[e]);
            uint32_t off = SWZ32(n, c) + kb;
            *reinterpret_cast<unsigned short*>(sb + off) =
                *reinterpret_cast<unsigned short*>(&hh);
        }
    }
    __syncthreads();

    unsigned char* oH = gBh + (size_t)(bn * KT + kt) * BLKB;
    {
        int o = tid * 16;
        *reinterpret_cast<uint4*>(oH + o) = *reinterpret_cast<uint4*>(sb + o);
        o += NTH * 16;
        *reinterpret_cast<uint4*>(oH + o) = *reinterpret_cast<uint4*>(sb + o);
    }
}

// ======================= Phase 2: GEMM + zero fill =======================

static __device__ __forceinline__ void issue_stage(
    uint32_t dst, size_t ablk, size_t bblk, int tid)
{
    const unsigned char* s0 = gAh + ablk * BLKB;
    const unsigned char* s1 = gBh + bblk * BLKB;
    const uint32_t t16 = tid * 16;
    #pragma unroll
    for (int h = 0; h < 2; ++h) {
        uint32_t off = t16 + h * 4096;
        CP16(dst + off,        s0 + off);
        CP16(dst + BLKB + off, s1 + off);
    }
}

__global__ __launch_bounds__(NTH, 2)
void trilmm_pp(float* __restrict__ C, int N)
{
    const int p   = blockIdx.x;
    const int tid = threadIdx.x;

    // ---- zero tiles (appended after the 2080 band tiles) ----
    if (p >= NWORK) {
        int q = p - NWORK;                 // 0..2015 over 63-row triangle
        int e = (int)((sqrtf(8.f * (float)q + 1.f) - 1.f) * 0.5f);
        while ((e + 1) * (e + 2) / 2 <= q) ++e;
        while (e * (e + 1) / 2 > q) --e;
        int y  = q - e * (e + 1) / 2;      // 0..e
        int bi = y, bj = e + 1;            // bi < bj
        const float4 z = make_float4(0.f, 0.f, 0.f, 0.f);
        float4* Cb = reinterpret_cast<float4*>(C + (size_t)bi * 128 * N + bj * 128);
        const int row_f4 = N / 4;
        #pragma unroll 4
        for (int i = tid; i < 128 * 32; i += NTH) {
            int r = i >> 5;
            int c = i & 31;
            Cb[(size_t)r * row_f4 + c] = z;
        }
        return;
    }

    // ---- band tiles: longest-band-first mapping ----
    int e = (int)((sqrtf(8.f * (float)p + 1.f) - 1.f) * 0.5f);
    while ((e + 1) * (e + 2) / 2 <= p) ++e;
    while (e * (e + 1) / 2 > p) --e;
    const int t  = p - e * (e + 1) / 2;
    const int d  = 63 - e;
    const int bj = t, bi = t + d;

    const int wid  = tid >> 5;
    const int lane = tid & 31;
    const int m0   = (wid >> 2) * 64;    // 2x4 warp grid, warp tile 64x32
    const int n0   = (wid & 3) * 32;

    extern __shared__ __align__(1024) unsigned char dsm[];
    const uint32_t S = smem_u32(dsm);

    float acc[4][4][4];
    #pragma unroll
    for (int a = 0; a < 4; ++a)
        #pragma unroll
        for (int b = 0; b < 4; ++b)
            #pragma unroll
            for (int c = 0; c < 4; ++c)
                acc[a][b][c] = 0.f;

    const int kt0 = 4 * bj;
    const int NT  = 4 * (bi - bj) + 4;   // 32-wide K stages in band (>= 4)
    const size_t abase = (size_t)bi * KT + kt0;
    const size_t bbase = (size_t)bj * KT + kt0;

    // prologue: stages 0..3
    issue_stage(S,              abase,     bbase,     tid); CP_COMMIT();
    issue_stage(S + STAGEB,     abase + 1, bbase + 1, tid); CP_COMMIT();
    issue_stage(S + 2 * STAGEB, abase + 2, bbase + 2, tid); CP_COMMIT();
    issue_stage(S + 3 * STAGEB, abase + 3, bbase + 3, tid); CP_COMMIT();

    const uint32_t a_r = (uint32_t)(lane & 15);
    const uint32_t a_c = (uint32_t)(lane >> 4);
    const uint32_t b_r = (uint32_t)((lane & 7) + ((lane >> 4) & 1) * 8);
    const uint32_t b_c = (uint32_t)((lane >> 3) & 1);

    int slot = 0, wslot = 4;
    for (int it = 0; it < NT; ++it) {
        CP_WAIT3();
        __syncthreads();
        if (it + 4 < NT)
            issue_stage(S + wslot * STAGEB,
                        abase + it + 4, bbase + it + 4, tid);
        CP_COMMIT();

        const uint32_t aS  = S + slot * STAGEB;
        const uint32_t bHS = aS + BLKB;

        #pragma unroll
        for (int kk = 0; kk < 2; ++kk) {
            uint32_t ah[4][4];
            #pragma unroll
            for (int mt = 0; mt < 4; ++mt) {
                uint32_t off = SWZ32(m0 + mt * 16 + a_r, kk * 2 + a_c);
                LDSM4(ah[mt], aS + off);
            }
            #pragma unroll
            for (int j2 = 0; j2 < 2; ++j2) {
                uint32_t bfh[4];
                uint32_t boff = SWZ32(n0 + j2 * 16 + b_r, kk * 2 + b_c);
                LDSM4(bfh, bHS + boff);
                #pragma unroll
                for (int mt = 0; mt < 4; ++mt) {
                    #pragma unroll
                    for (int jj = 0; jj < 2; ++jj) {
                        float* dd = acc[mt][j2 * 2 + jj];
                        MMA16816(dd, ah[mt], bfh[2 * jj], bfh[2 * jj + 1]);
                    }
                }
            }
        }
        if (++slot == STAGES)  slot = 0;
        if (++wslot == STAGES) wslot = 0;
    }

    // epilogue: registers -> C, tril mask on diagonal tiles
    const int g   = lane >> 2;
    const int tig = lane & 3;
    const bool diag = (bi == bj);
    #pragma unroll
    for (int mt = 0; mt < 4; ++mt) {
        #pragma unroll
        for (int j = 0; j < 4; ++j) {
            int row0 = m0 + mt * 16 + g;
            int col  = n0 + j * 8 + 2 * tig;
            float c0 = acc[mt][j][0], c1 = acc[mt][j][1];
            float c2 = acc[mt][j][2], c3 = acc[mt][j][3];
            if (diag) {
                if (col     > row0)     c0 = 0.f;
                if (col + 1 > row0)     c1 = 0.f;
                if (col     > row0 + 8) c2 = 0.f;
                if (col + 1 > row0 + 8) c3 = 0.f;
            }
            float* p0 = C + (size_t)(bi * 128 + row0) * N + bj * 128 + col;
            float* p1 = p0 + (size_t)8 * N;
            *reinterpret_cast<float2*>(p0) = make_float2(c0, c1);
            *reinterpret_cast<float2*>(p1) = make_float2(c2, c3);
        }
    }
}

extern "C" void kernel_launch(void* const* d_in, const int* in_sizes, int n_in,
                              void* d_out, int out_size)
{
    const float* A = (const float*)d_in[0];
    const float* B = (const float*)d_in[1];
    float* C = (float*)d_out;
    int N = (int)llround(sqrt((double)in_sizes[0]));   // 8192

    cudaFuncSetAttribute(trilmm_pp,
                         cudaFuncAttributeMaxDynamicSharedMemorySize, SMEM_REQ);

    dim3 gridConv(KT, NB);
    convA<<<gridConv, NTH>>>(A, N);
    convB<<<gridConv, NTH>>>(B, N);

    trilmm_pp<<<NB * NB, NTH, SMEM_REQ>>>(C, N);   // 2080 band + 2016 zero
}

// round 15
// speedup vs baseline: 1.0346x; 1.0207x over previous
#include <cuda_runtime.h>
#include <cuda_fp16.h>
#include <stdint.h>
#include <math.h>

// C = tril(A @ B), A,B lower-triangular fp32, N = 8192.
// Plain fp16 HMMA (Ah*Bh, fp32 accumulate); rel_err ~2.9e-4 (measured).
// Phase 1: ONE fused conv kernel, 1D grid over exactly the band blocks
//          (8320 A-jobs then 8320 B-jobs) -> pre-swizzled 128x32 fp16 blocks.
// Phase 2: single kernel, 1D grid: 2080 band tiles (longest-band-first)
//          followed by 2016 zero tiles. Band: 128x128 CTA tile, BK=32,
//          4-stage x 16KB cp.async ring (WAIT2, issue at it+3), 8 warps
//          (warp tile 64x32), 2 CTAs/SM.

#define NTH 256
#define NB  64            // 128-wide block count (N/128)
#define KT  256           // 32-wide k-tile count (N/32)
#define BLKB 8192         // bytes per 128x32 fp16 block
#define STAGEB (2 * BLKB) // Ah + Bh = 16 KB
#define STAGES 4
#define SMEM_REQ (STAGES * STAGEB)   // 64 KB
#define NWORK (NB * (NB + 1) / 2)    // 2080 band tiles
#define NCONV 8320                   // band blocks per matrix: 4*2080

// swizzled offset inside a 128x32 block: row r (0..127), 16B chunk c (0..3)
#define SWZ32(r, c) ((uint32_t)((r) * 64 + ((((c) ^ (((r) >> 1) & 3))) << 4)))

__device__ __align__(1024) static unsigned char gAh[(size_t)NB * KT * BLKB];
__device__ __align__(1024) static unsigned char gBh[(size_t)NB * KT * BLKB];

static __device__ __forceinline__ uint32_t smem_u32(const void* p) {
    uint32_t a;
    asm("{ .reg .u64 t; cvta.to.shared.u64 t, %1; cvt.u32.u64 %0, t; }"
        : "=r"(a) : "l"(p));
    return a;
}

#define LDSM4(r, addr)                                                    \
    asm volatile("ldmatrix.sync.aligned.m8n8.x4.shared.b16 "              \
                 "{%0, %1, %2, %3}, [%4];"                                \
                 : "=r"((r)[0]), "=r"((r)[1]), "=r"((r)[2]), "=r"((r)[3]) \
                 : "r"(addr))

#define MMA16816(d, a, b0, b1)                                            \
    asm volatile("mma.sync.aligned.m16n8k16.row.col.f32.f16.f16.f32 "     \
                 "{%0, %1, %2, %3}, {%4, %5, %6, %7}, {%8, %9}, "         \
                 "{%0, %1, %2, %3};"                                      \
                 : "+f"((d)[0]), "+f"((d)[1]), "+f"((d)[2]), "+f"((d)[3]) \
                 : "r"((a)[0]), "r"((a)[1]), "r"((a)[2]), "r"((a)[3]),    \
                   "r"(b0), "r"(b1))

#define CP16(dst, src)                                                    \
    asm volatile("cp.async.cg.shared.global [%0], [%1], 16;"              \
                 :: "r"(dst), "l"(src))
#define CP_COMMIT() asm volatile("cp.async.commit_group;" ::: "memory")
#define CP_WAIT2()  asm volatile("cp.async.wait_group 2;" ::: "memory")

// map q in [0, 4*NWORK) -> (row_blk, kt): row_blk has 4*(row_blk+1) k-tiles
static __device__ __forceinline__ void band_block(int q, int& rb, int& kt)
{
    // q = sum_{r<rb} 4(r+1) + kt = 2*rb*(rb+1) + kt,  kt in [0, 4rb+4)
    int r = (int)((sqrtf(2.f * (float)q + 1.f) - 1.f) * 0.5f);
    while (2 * (r + 1) * (r + 2) <= q) ++r;
    while (2 * r * (r + 1) > q) --r;
    rb = r;
    kt = q - 2 * r * (r + 1);
}

// ======================= Phase 1: fused conversion =======================

__global__ __launch_bounds__(NTH, 4)
void convAB(const float* __restrict__ A, const float* __restrict__ B, int N)
{
    const int tid = threadIdx.x;
    const int job = blockIdx.x;

    if (job < NCONV) {
        // ---- A job: block (bi, kt), rows m, k-contig in global ----
        int bi, kt;
        band_block(job, bi, kt);
        const float* Ab = A + (size_t)(bi * 128) * N + kt * 32;
        unsigned char* oH = gAh + (size_t)(bi * KT + kt) * BLKB;
        #pragma unroll
        for (int l = 0; l < 4; ++l) {
            int idx = tid + l * NTH;      // 0..1023
            int r  = idx >> 3;            // m row
            int c4 = idx & 7;             // float4 index along k
            float4 v = *reinterpret_cast<const float4*>(Ab + (size_t)r * N + c4 * 4);
            uint32_t h01, h23;
            asm("cvt.rn.f16x2.f32 %0, %1, %2;" : "=r"(h01) : "f"(v.y), "f"(v.x));
            asm("cvt.rn.f16x2.f32 %0, %1, %2;" : "=r"(h23) : "f"(v.w), "f"(v.z));
            uint32_t off = SWZ32(r, c4 >> 1) + (c4 & 1) * 8;
            *reinterpret_cast<uint2*>(oH + off) = make_uint2(h01, h23);
        }
        return;
    }

    // ---- B job: block (bn, kt) with kt >= 4*bn; transpose via smem ----
    // Reuse the A map on (job - NCONV): (rb, j) with j in [0, 4rb+4);
    // set bn = 63 - rb, kt = 255 - j  ->  kt in [4bn, 255] exactly.
    {
        int rb, j;
        band_block(job - NCONV, rb, j);
        int bn = 63 - rb;
        int kt = 255 - j;

        __shared__ __align__(128) unsigned char sb[BLKB];
        const float* Bb = B + (size_t)(kt * 32) * N + bn * 128;
        #pragma unroll
        for (int l = 0; l < 4; ++l) {
            int idx = tid + l * NTH;      // 0..1023
            int k  = idx >> 5;            // 0..31
            int n4 = idx & 31;            // float4 index along n
            float4 v = *reinterpret_cast<const float4*>(Bb + (size_t)k * N + n4 * 4);
            const float* pv = &v.x;
            int c  = k >> 3;
            int kb = (k & 7) * 2;
            #pragma unroll
            for (int e2 = 0; e2 < 4; ++e2) {
                int n = n4 * 4 + e2;
                __half hh = __float2half_rn(pv[e2]);
                uint32_t off = SWZ32(n, c) + kb;
                *reinterpret_cast<unsigned short*>(sb + off) =
                    *reinterpret_cast<unsigned short*>(&hh);
            }
        }
        __syncthreads();

        unsigned char* oH = gBh + (size_t)(bn * KT + kt) * BLKB;
        int o = tid * 16;
        *reinterpret_cast<uint4*>(oH + o) = *reinterpret_cast<uint4*>(sb + o);
        o += NTH * 16;
        *reinterpret_cast<uint4*>(oH + o) = *reinterpret_cast<uint4*>(sb + o);
    }
}

// ======================= Phase 2: GEMM + zero fill =======================

static __device__ __forceinline__ void issue_stage(
    uint32_t dst, size_t ablk, size_t bblk, int tid)
{
    const unsigned char* s0 = gAh + ablk * BLKB;
    const unsigned char* s1 = gBh + bblk * BLKB;
    const uint32_t t16 = tid * 16;
    #pragma unroll
    for (int h = 0; h < 2; ++h) {
        uint32_t off = t16 + h * 4096;
        CP16(dst + off,        s0 + off);
        CP16(dst + BLKB + off, s1 + off);
    }
}

__global__ __launch_bounds__(NTH, 2)
void trilmm_pp(float* __restrict__ C, int N)
{
    const int p   = blockIdx.x;
    const int tid = threadIdx.x;

    // ---- zero tiles (appended after the 2080 band tiles) ----
    if (p >= NWORK) {
        int q = p - NWORK;                 // 0..2015 over 63-row triangle
        int e = (int)((sqrtf(8.f * (float)q + 1.f) - 1.f) * 0.5f);
        while ((e + 1) * (e + 2) / 2 <= q) ++e;
        while (e * (e + 1) / 2 > q) --e;
        int y  = q - e * (e + 1) / 2;      // 0..e
        int bi = y, bj = e + 1;            // bi < bj
        const float4 z = make_float4(0.f, 0.f, 0.f, 0.f);
        float4* Cb = reinterpret_cast<float4*>(C + (size_t)bi * 128 * N + bj * 128);
        const int row_f4 = N / 4;
        #pragma unroll 4
        for (int i = tid; i < 128 * 32; i += NTH) {
            int r = i >> 5;
            int c = i & 31;
            Cb[(size_t)r * row_f4 + c] = z;
        }
        return;
    }

    // ---- band tiles: longest-band-first mapping ----
    int e = (int)((sqrtf(8.f * (float)p + 1.f) - 1.f) * 0.5f);
    while ((e + 1) * (e + 2) / 2 <= p) ++e;
    while (e * (e + 1) / 2 > p) --e;
    const int t  = p - e * (e + 1) / 2;
    const int d  = 63 - e;
    const int bj = t, bi = t + d;

    const int wid  = tid >> 5;
    const int lane = tid & 31;
    const int m0   = (wid >> 2) * 64;    // 2x4 warp grid, warp tile 64x32
    const int n0   = (wid & 3) * 32;

    extern __shared__ __align__(1024) unsigned char dsm[];
    const uint32_t S = smem_u32(dsm);

    float acc[4][4][4];
    #pragma unroll
    for (int a = 0; a < 4; ++a)
        #pragma unroll
        for (int b = 0; b < 4; ++b)
            #pragma unroll
            for (int c = 0; c < 4; ++c)
                acc[a][b][c] = 0.f;

    const int kt0 = 4 * bj;
    const int NT  = 4 * (bi - bj) + 4;   // 32-wide K stages in band (>= 4)
    const size_t abase = (size_t)bi * KT + kt0;
    const size_t bbase = (size_t)bj * KT + kt0;

    // prologue: stages 0..2
    issue_stage(S,              abase,     bbase,     tid); CP_COMMIT();
    issue_stage(S + STAGEB,     abase + 1, bbase + 1, tid); CP_COMMIT();
    issue_stage(S + 2 * STAGEB, abase + 2, bbase + 2, tid); CP_COMMIT();

    const uint32_t a_r = (uint32_t)(lane & 15);
    const uint32_t a_c = (uint32_t)(lane >> 4);
    const uint32_t b_r = (uint32_t)((lane & 7) + ((lane >> 4) & 1) * 8);
    const uint32_t b_c = (uint32_t)((lane >> 3) & 1);

    for (int it = 0; it < NT; ++it) {
        CP_WAIT2();
        __syncthreads();
        if (it + 3 < NT)
            issue_stage(S + ((it + 3) & 3) * STAGEB,
                        abase + it + 3, bbase + it + 3, tid);
        CP_COMMIT();

        const uint32_t aS  = S + (it & 3) * STAGEB;
        const uint32_t bHS = aS + BLKB;

        #pragma unroll
        for (int kk = 0; kk < 2; ++kk) {
            uint32_t ah[4][4];
            #pragma unroll
            for (int mt = 0; mt < 4; ++mt) {
                uint32_t off = SWZ32(m0 + mt * 16 + a_r, kk * 2 + a_c);
                LDSM4(ah[mt], aS + off);
            }
            #pragma unroll
            for (int j2 = 0; j2 < 2; ++j2) {
                uint32_t bfh[4];
                uint32_t boff = SWZ32(n0 + j2 * 16 + b_r, kk * 2 + b_c);
                LDSM4(bfh, bHS + boff);
                #pragma unroll
                for (int mt = 0; mt < 4; ++mt) {
                    #pragma unroll
                    for (int jj = 0; jj < 2; ++jj) {
                        float* dd = acc[mt][j2 * 2 + jj];
                        MMA16816(dd, ah[mt], bfh[2 * jj], bfh[2 * jj + 1]);
                    }
                }
            }
        }
    }

    // epilogue: registers -> C, tril mask on diagonal tiles
    const int g   = lane >> 2;
    const int tig = lane & 3;
    const bool diag = (bi == bj);
    #pragma unroll
    for (int mt = 0; mt < 4; ++mt) {
        #pragma unroll
        for (int j = 0; j < 4; ++j) {
            int row0 = m0 + mt * 16 + g;
            int col  = n0 + j * 8 + 2 * tig;
            float c0 = acc[mt][j][0], c1 = acc[mt][j][1];
            float c2 = acc[mt][j][2], c3 = acc[mt][j][3];
            if (diag) {
                if (col     > row0)     c0 = 0.f;
                if (col + 1 > row0)     c1 = 0.f;
                if (col     > row0 + 8) c2 = 0.f;
                if (col + 1 > row0 + 8) c3 = 0.f;
            }
            float* p0 = C + (size_t)(bi * 128 + row0) * N + bj * 128 + col;
            float* p1 = p0 + (size_t)8 * N;
            *reinterpret_cast<float2*>(p0) = make_float2(c0, c1);
            *reinterpret_cast<float2*>(p1) = make_float2(c2, c3);
        }
    }
}

extern "C" void kernel_launch(void* const* d_in, const int* in_sizes, int n_in,
                              void* d_out, int out_size)
{
    const float* A = (const float*)d_in[0];
    const float* B = (const float*)d_in[1];
    float* C = (float*)d_out;
    int N = (int)llround(sqrt((double)in_sizes[0]));   // 8192

    cudaFuncSetAttribute(trilmm_pp,
                         cudaFuncAttributeMaxDynamicSharedMemorySize, SMEM_REQ);

    convAB<<<2 * NCONV, NTH>>>(A, B, N);           // 16640 band-block jobs
    trilmm_pp<<<NB * NB, NTH, SMEM_REQ>>>(C, N);   // 2080 band + 2016 zero
}

// round 17
// speedup vs baseline: 1.1046x; 1.0676x over previous
#include <cuda_runtime.h>
#include <cuda_fp16.h>
#include <stdint.h>
#include <math.h>

// C = tril(A @ B), A,B lower-triangular fp32, N = 8192.
// Plain fp16 HMMA (Ah*Bh, fp32 accumulate); rel_err ~2.9e-4 (measured).
// Phase 1: ONE fused conv kernel, 1D grid over exactly the band blocks
//          (8320 A-jobs then 8320 B-jobs). B transpose done in registers
//          (coalesced strided loads) + conflict-free st.shared.v4.
// Phase 2: single kernel, 1D grid: 2080 band tiles (longest-band-first)
//          followed by 2016 zero tiles. Band: 128x128 CTA tile, BK=32,
//          4-stage x 16KB cp.async ring (WAIT2, issue at it+3), 8 warps
//          (warp tile 64x32), 2 CTAs/SM.

#define NTH 256
#define NB  64            // 128-wide block count (N/128)
#define KT  256           // 32-wide k-tile count (N/32)
#define BLKB 8192         // bytes per 128x32 fp16 block
#define STAGEB (2 * BLKB) // Ah + Bh = 16 KB
#define STAGES 4
#define SMEM_REQ (STAGES * STAGEB)   // 64 KB
#define NWORK (NB * (NB + 1) / 2)    // 2080 band tiles
#define NCONV 8320                   // band blocks per matrix: 4*2080

// swizzled offset inside a 128x32 block: row r (0..127), 16B chunk c (0..3)
#define SWZ32(r, c) ((uint32_t)((r) * 64 + ((((c) ^ (((r) >> 1) & 3))) << 4)))

__device__ __align__(1024) static unsigned char gAh[(size_t)NB * KT * BLKB];
__device__ __align__(1024) static unsigned char gBh[(size_t)NB * KT * BLKB];

static __device__ __forceinline__ uint32_t smem_u32(const void* p) {
    uint32_t a;
    asm("{ .reg .u64 t; cvta.to.shared.u64 t, %1; cvt.u32.u64 %0, t; }"
        : "=r"(a) : "l"(p));
    return a;
}

#define LDSM4(r, addr)                                                    \
    asm volatile("ldmatrix.sync.aligned.m8n8.x4.shared.b16 "              \
                 "{%0, %1, %2, %3}, [%4];"                                \
                 : "=r"((r)[0]), "=r"((r)[1]), "=r"((r)[2]), "=r"((r)[3]) \
                 : "r"(addr))

#define MMA16816(d, a, b0, b1)                                            \
    asm volatile("mma.sync.aligned.m16n8k16.row.col.f32.f16.f16.f32 "     \
                 "{%0, %1, %2, %3}, {%4, %5, %6, %7}, {%8, %9}, "         \
                 "{%0, %1, %2, %3};"                                      \
                 : "+f"((d)[0]), "+f"((d)[1]), "+f"((d)[2]), "+f"((d)[3]) \
                 : "r"((a)[0]), "r"((a)[1]), "r"((a)[2]), "r"((a)[3]),    \
                   "r"(b0), "r"(b1))

#define CP16(dst, src)                                                    \
    asm volatile("cp.async.cg.shared.global [%0], [%1], 16;"              \
                 :: "r"(dst), "l"(src))
#define CP_COMMIT() asm volatile("cp.async.commit_group;" ::: "memory")
#define CP_WAIT2()  asm volatile("cp.async.wait_group 2;" ::: "memory")

// map q in [0, 4*NWORK) -> (row_blk, kt): row_blk has 4*(row_blk+1) k-tiles
static __device__ __forceinline__ void band_block(int q, int& rb, int& kt)
{
    int r = (int)((sqrtf(2.f * (float)q + 1.f) - 1.f) * 0.5f);
    while (2 * (r + 1) * (r + 2) <= q) ++r;
    while (2 * r * (r + 1) > q) --r;
    rb = r;
    kt = q - 2 * r * (r + 1);
}

// ======================= Phase 1: fused conversion =======================

__global__ __launch_bounds__(NTH, 4)
void convAB(const float* __restrict__ A, const float* __restrict__ B, int N)
{
    const int tid = threadIdx.x;
    const int job = blockIdx.x;

    if (job < NCONV) {
        // ---- A job: block (bi, kt), rows m, k-contig in global ----
        int bi, kt;
        band_block(job, bi, kt);
        const float* Ab = A + (size_t)(bi * 128) * N + kt * 32;
        unsigned char* oH = gAh + (size_t)(bi * KT + kt) * BLKB;
        #pragma unroll
        for (int l = 0; l < 4; ++l) {
            int idx = tid + l * NTH;      // 0..1023
            int r  = idx >> 3;            // m row
            int c4 = idx & 7;             // float4 index along k
            float4 v = *reinterpret_cast<const float4*>(Ab + (size_t)r * N + c4 * 4);
            uint32_t h01, h23;
            asm("cvt.rn.f16x2.f32 %0, %1, %2;" : "=r"(h01) : "f"(v.y), "f"(v.x));
            asm("cvt.rn.f16x2.f32 %0, %1, %2;" : "=r"(h23) : "f"(v.w), "f"(v.z));
            uint32_t off = SWZ32(r, c4 >> 1) + (c4 & 1) * 8;
            *reinterpret_cast<uint2*>(oH + off) = make_uint2(h01, h23);
        }
        return;
    }

    // ---- B job: block (bn, kt) with kt >= 4*bn; register transpose ----
    // Map: (rb, j) from A map; bn = 63 - rb, kt = 255 - j (exactly the band).
    {
        int rb, j;
        band_block(job - NCONV, rb, j);
        int bn = 63 - rb;
        int kt = 255 - j;

        __shared__ __align__(128) unsigned char sb[BLKB];
        const float* Bb = B + (size_t)(kt * 32) * N + bn * 128;

        const int n = tid & 127;          // output row (n)
        const int c0 = tid >> 7;          // 0..1; chunks c0 and c0+2
        #pragma unroll
        for (int cc = 0; cc < 2; ++cc) {
            int c = c0 + cc * 2;          // 16B chunk = 8 k-values
            const float* g = Bb + (size_t)(c * 8) * N + n;
            uint32_t w[4];
            #pragma unroll
            for (int q2 = 0; q2 < 4; ++q2) {
                float f0 = g[(size_t)(2 * q2) * N];
                float f1 = g[(size_t)(2 * q2 + 1) * N];
                asm("cvt.rn.f16x2.f32 %0, %1, %2;" : "=r"(w[q2]) : "f"(f1), "f"(f0));
            }
            uint32_t soff = smem_u32(sb) + SWZ32(n, c);
            asm volatile("st.shared.v4.b32 [%0], {%1, %2, %3, %4};"
                         :: "r"(soff), "r"(w[0]), "r"(w[1]), "r"(w[2]), "r"(w[3]));
        }
        __syncthreads();

        unsigned char* oH = gBh + (size_t)(bn * KT + kt) * BLKB;
        int o = tid * 16;
        *reinterpret_cast<uint4*>(oH + o) = *reinterpret_cast<uint4*>(sb + o);
        o += NTH * 16;
        *reinterpret_cast<uint4*>(oH + o) = *reinterpret_cast<uint4*>(sb + o);
    }
}

// ======================= Phase 2: GEMM + zero fill =======================

static __device__ __forceinline__ void issue_stage(
    uint32_t dst, size_t ablk, size_t bblk, int tid)
{
    const unsigned char* s0 = gAh + ablk * BLKB;
    const unsigned char* s1 = gBh + bblk * BLKB;
    const uint32_t t16 = tid * 16;
    #pragma unroll
    for (int h = 0; h < 2; ++h) {
        uint32_t off = t16 + h * 4096;
        CP16(dst + off,        s0 + off);
        CP16(dst + BLKB + off, s1 + off);
    }
}

__global__ __launch_bounds__(NTH, 2)
void trilmm_pp(float* __restrict__ C, int N)
{
    const int p   = blockIdx.x;
    const int tid = threadIdx.x;

    // ---- zero tiles (appended after the 2080 band tiles) ----
    if (p >= NWORK) {
        int q = p - NWORK;                 // 0..2015 over 63-row triangle
        int e = (int)((sqrtf(8.f * (float)q + 1.f) - 1.f) * 0.5f);
        while ((e + 1) * (e + 2) / 2 <= q) ++e;
        while (e * (e + 1) / 2 > q) --e;
        int y  = q - e * (e + 1) / 2;      // 0..e
        int bi = y, bj = e + 1;            // bi < bj
        const float4 z = make_float4(0.f, 0.f, 0.f, 0.f);
        float4* Cb = reinterpret_cast<float4*>(C + (size_t)bi * 128 * N + bj * 128);
        const int row_f4 = N / 4;
        #pragma unroll 4
        for (int i = tid; i < 128 * 32; i += NTH) {
            int r = i >> 5;
            int c = i & 31;
            Cb[(size_t)r * row_f4 + c] = z;
        }
        return;
    }

    // ---- band tiles: longest-band-first mapping ----
    int e = (int)((sqrtf(8.f * (float)p + 1.f) - 1.f) * 0.5f);
    while ((e + 1) * (e + 2) / 2 <= p) ++e;
    while (e * (e + 1) / 2 > p) --e;
    const int t  = p - e * (e + 1) / 2;
    const int d  = 63 - e;
    const int bj = t, bi = t + d;

    const int wid  = tid >> 5;
    const int lane = tid & 31;
    const int m0   = (wid >> 2) * 64;    // 2x4 warp grid, warp tile 64x32
    const int n0   = (wid & 3) * 32;

    extern __shared__ __align__(1024) unsigned char dsm[];
    const uint32_t S = smem_u32(dsm);

    float acc[4][4][4];
    #pragma unroll
    for (int a = 0; a < 4; ++a)
        #pragma unroll
        for (int b = 0; b < 4; ++b)
            #pragma unroll
            for (int c = 0; c < 4; ++c)
                acc[a][b][c] = 0.f;

    const int kt0 = 4 * bj;
    const int NT  = 4 * (bi - bj) + 4;   // 32-wide K stages in band (>= 4)
    const size_t abase = (size_t)bi * KT + kt0;
    const size_t bbase = (size_t)bj * KT + kt0;

    // prologue: stages 0..2
    issue_stage(S,              abase,     bbase,     tid); CP_COMMIT();
    issue_stage(S + STAGEB,     abase + 1, bbase + 1, tid); CP_COMMIT();
    issue_stage(S + 2 * STAGEB, abase + 2, bbase + 2, tid); CP_COMMIT();

    const uint32_t a_r = (uint32_t)(lane & 15);
    const uint32_t a_c = (uint32_t)(lane >> 4);
    const uint32_t b_r = (uint32_t)((lane & 7) + ((lane >> 4) & 1) * 8);
    const uint32_t b_c = (uint32_t)((lane >> 3) & 1);

    for (int it = 0; it < NT; ++it) {
        CP_WAIT2();
        __syncthreads();
        if (it + 3 < NT)
            issue_stage(S + ((it + 3) & 3) * STAGEB,
                        abase + it + 3, bbase + it + 3, tid);
        CP_COMMIT();

        const uint32_t aS  = S + (it & 3) * STAGEB;
        const uint32_t bHS = aS + BLKB;

        #pragma unroll
        for (int kk = 0; kk < 2; ++kk) {
            uint32_t ah[4][4];
            #pragma unroll
            for (int mt = 0; mt < 4; ++mt) {
                uint32_t off = SWZ32(m0 + mt * 16 + a_r, kk * 2 + a_c);
                LDSM4(ah[mt], aS + off);
            }
            #pragma unroll
            for (int j2 = 0; j2 < 2; ++j2) {
                uint32_t bfh[4];
                uint32_t boff = SWZ32(n0 + j2 * 16 + b_r, kk * 2 + b_c);
                LDSM4(bfh, bHS + boff);
                #pragma unroll
                for (int mt = 0; mt < 4; ++mt) {
                    #pragma unroll
                    for (int jj = 0; jj < 2; ++jj) {
                        float* dd = acc[mt][j2 * 2 + jj];
                        MMA16816(dd, ah[mt], bfh[2 * jj], bfh[2 * jj + 1]);
                    }
                }
            }
        }
    }

    // epilogue: registers -> C, tril mask on diagonal tiles
    const int g   = lane >> 2;
    const int tig = lane & 3;
    const bool diag = (bi == bj);
    #pragma unroll
    for (int mt = 0; mt < 4; ++mt) {
        #pragma unroll
        for (int j = 0; j < 4; ++j) {
            int row0 = m0 + mt * 16 + g;
            int col  = n0 + j * 8 + 2 * tig;
            float c0 = acc[mt][j][0], c1 = acc[mt][j][1];
            float c2 = acc[mt][j][2], c3 = acc[mt][j][3];
            if (diag) {
                if (col     > row0)     c0 = 0.f;
                if (col + 1 > row0)     c1 = 0.f;
                if (col     > row0 + 8) c2 = 0.f;
                if (col + 1 > row0 + 8) c3 = 0.f;
            }
            float* p0 = C + (size_t)(bi * 128 + row0) * N + bj * 128 + col;
            float* p1 = p0 + (size_t)8 * N;
            *reinterpret_cast<float2*>(p0) = make_float2(c0, c1);
            *reinterpret_cast<float2*>(p1) = make_float2(c2, c3);
        }
    }
}

extern "C" void kernel_launch(void* const* d_in, const int* in_sizes, int n_in,
                              void* d_out, int out_size)
{
    const float* A = (const float*)d_in[0];
    const float* B = (const float*)d_in[1];
    float* C = (float*)d_out;
    int N = (int)llround(sqrt((double)in_sizes[0]));   // 8192

    cudaFuncSetAttribute(trilmm_pp,
                         cudaFuncAttributeMaxDynamicSharedMemorySize, SMEM_REQ);

    convAB<<<2 * NCONV, NTH>>>(A, B, N);           // 16640 band-block jobs
    trilmm_pp<<<NB * NB, NTH, SMEM_REQ>>>(C, N);   // 2080 band + 2016 zero
}